// round 12
// baseline (speedup 1.0000x reference)
#include <cuda_runtime.h>
#include <math_constants.h>

#define NX   1000
#define NP   1008        // padded shared hist (bin 1000 possible; folded into 999)
#define HB   592         // 4 CTAs/SM x 148 SMs -> ALL resident (barrier-safe)
#define HT   512
#define TQ   8           // float4s per thread per tile
#define TILE (HT * TQ)   // 4096 float4 = 64KB per tile

// ---------------- device-global scratch (zero-init is the neutral state) ----
__device__ unsigned int g_negmin_bits;   // holds max(~enc(v))  -> min value
__device__ unsigned int g_max_bits;      // holds max( enc(v))  -> max value
__device__ unsigned int g_hist[2][NX];
__device__ unsigned int g_bar;           // grid barrier counter
__device__ unsigned int g_ticket;        // last-block detection
__device__ unsigned int g_workA;         // phase-A tile queue
__device__ unsigned int g_workB;         // phase-B tile queue

__device__ __forceinline__ unsigned int enc_f(float f) {
    unsigned int u = __float_as_uint(f);
    return (u & 0x80000000u) ? ~u : (u | 0x80000000u);
}
__device__ __forceinline__ float dec_f(unsigned int u) {
    u = (u & 0x80000000u) ? (u & 0x7FFFFFFFu) : ~u;
    return __uint_as_float(u);
}

// The linspace grid point, matching f32 "lo + j*step" with exact endpoint.
__device__ __forceinline__ float xval(int j, float lo, float hi, float step) {
    return (j >= NX - 1) ? hi : fmaf((float)j, step, lo);
}

// Cheap bin: ceil_to_int((v-lo)/step), NO clamp — j in [0,1000]; padded
// shared hist absorbs 1000, folded into 999 at flush (exact).
__device__ __forceinline__ int binof(float v, float invstep, float negloinv) {
    return __float2int_ru(fmaf(v, invstep, negloinv));   // F2I.RP
}

__device__ __forceinline__ void mm4(float4 v, float& mn, float& mx) {
    mn = fminf(mn, fminf(fminf(v.x, v.y), fminf(v.z, v.w)));
    mx = fmaxf(mx, fmaxf(fmaxf(v.x, v.y), fmaxf(v.z, v.w)));
}
__device__ __forceinline__ void hist4(float4 v, unsigned int* h,
                                      float invstep, float negloinv) {
    atomicAdd(&h[binof(v.x, invstep, negloinv)], 1u);
    atomicAdd(&h[binof(v.y, invstep, negloinv)], 1u);
    atomicAdd(&h[binof(v.z, invstep, negloinv)], 1u);
    atomicAdd(&h[binof(v.w, invstep, negloinv)], 1u);
}

// =================== single fused persistent kernel =========================
__global__ void __launch_bounds__(HT, 4) crps_k(const float* __restrict__ a,
                                                const float* __restrict__ b,
                                                int n, float* __restrict__ out) {
    __shared__ unsigned int sh[NP];      // this block's histogram (both arrays)
    __shared__ unsigned int sh1b[NP];    // second hist: array b bins
    __shared__ float smn[16], smx[16];
    __shared__ double sd[16];
    __shared__ unsigned int ws0[16], ws1[16];
    __shared__ unsigned int s_last;
    __shared__ int s_tile;

    const int t    = threadIdx.x;
    const int lane = t & 31, w = t >> 5;    // 16 warps

    const float4* __restrict__ a4 = (const float4*)a;
    const float4* __restrict__ b4 = (const float4*)b;

    const int n4        = n >> 2;
    const int tilesArr  = (n4 + TILE - 1) / TILE;
    const int tilesAll  = 2 * tilesArr;

    for (int i = t; i < NP; i += HT) { sh[i] = 0u; sh1b[i] = 0u; }

    // ---------------- phase A: min/max, dynamic tile stealing ---------------
    float mn = CUDART_INF_F, mx = -CUDART_INF_F;
    for (;;) {
        __syncthreads();
        if (t == 0) s_tile = (int)atomicAdd(&g_workA, 1u);
        __syncthreads();
        int tile = s_tile;
        if (tile >= tilesAll) break;
        int which = tile & 1;
        int ti = tile >> 1;
        const float4* __restrict__ s4 = which ? b4 : a4;
        int base = ti * TILE + t;
        if ((ti + 1) * TILE <= n4) {                 // full tile, no guards
            #pragma unroll
            for (int g = 0; g < TQ / 4; ++g) {
                float4 v0 = s4[base + (4 * g + 0) * HT];
                float4 v1 = s4[base + (4 * g + 1) * HT];
                float4 v2 = s4[base + (4 * g + 2) * HT];
                float4 v3 = s4[base + (4 * g + 3) * HT];
                mm4(v0, mn, mx);
                mm4(v1, mn, mx);
                mm4(v2, mn, mx);
                mm4(v3, mn, mx);
            }
        } else {                                      // partial last tile
            #pragma unroll
            for (int k = 0; k < TQ; ++k) {
                int idx = base + k * HT;
                if (idx < n4) { float4 v = s4[idx]; mm4(v, mn, mx); }
            }
        }
    }
    if (blockIdx.x == 0 && t == 0) {     // scalar tail (n % 4), both arrays
        for (int k = (n4 << 2); k < n; ++k) {
            mn = fminf(mn, fminf(a[k], b[k]));
            mx = fmaxf(mx, fmaxf(a[k], b[k]));
        }
    }
    for (int o = 16; o; o >>= 1) {
        mn = fminf(mn, __shfl_xor_sync(0xFFFFFFFFu, mn, o));
        mx = fmaxf(mx, __shfl_xor_sync(0xFFFFFFFFu, mx, o));
    }
    if (lane == 0) { smn[w] = mn; smx[w] = mx; }
    __syncthreads();
    if (t < 32) {
        mn = (t < 16) ? smn[t] : CUDART_INF_F;
        mx = (t < 16) ? smx[t] : -CUDART_INF_F;
        for (int o = 16; o; o >>= 1) {
            mn = fminf(mn, __shfl_xor_sync(0xFFFFFFFFu, mn, o));
            mx = fmaxf(mx, __shfl_xor_sync(0xFFFFFFFFu, mx, o));
        }
        if (t == 0) {
            atomicMax(&g_negmin_bits, ~enc_f(mn));
            atomicMax(&g_max_bits, enc_f(mx));
        }
    }
    __syncthreads();

    // ---------------- grid barrier (all 592 CTAs resident -> safe) ----------
    if (t == 0) {
        __threadfence();
        atomicAdd(&g_bar, 1u);
        while (*((volatile unsigned int*)&g_bar) < HB) __nanosleep(64);
    }
    __syncthreads();
    __threadfence();

    // ---------------- phase B: histograms, dynamic tile stealing ------------
    float lo = dec_f(~__ldcg(&g_negmin_bits));
    float hi = dec_f(__ldcg(&g_max_bits));
    float step = (hi - lo) / (float)(NX - 1);
    float invstep = (step > 0.0f) ? (1.0f / step) : 0.0f;
    float negloinv = -lo * invstep;

    for (;;) {
        __syncthreads();
        if (t == 0) s_tile = (int)atomicAdd(&g_workB, 1u);
        __syncthreads();
        int tile = s_tile;
        if (tile >= tilesAll) break;
        int which = tile & 1;
        int ti = tile >> 1;
        const float4* __restrict__ s4 = which ? b4 : a4;
        unsigned int* h = which ? sh1b : sh;
        int base = ti * TILE + t;
        if ((ti + 1) * TILE <= n4) {                 // full tile
            #pragma unroll
            for (int g = 0; g < TQ / 4; ++g) {
                float4 v0 = s4[base + (4 * g + 0) * HT];
                float4 v1 = s4[base + (4 * g + 1) * HT];
                float4 v2 = s4[base + (4 * g + 2) * HT];
                float4 v3 = s4[base + (4 * g + 3) * HT];
                hist4(v0, h, invstep, negloinv);
                hist4(v1, h, invstep, negloinv);
                hist4(v2, h, invstep, negloinv);
                hist4(v3, h, invstep, negloinv);
            }
        } else {
            #pragma unroll
            for (int k = 0; k < TQ; ++k) {
                int idx = base + k * HT;
                if (idx < n4) { float4 v = s4[idx]; hist4(v, h, invstep, negloinv); }
            }
        }
    }
    if (blockIdx.x == 0 && t == 0) {     // scalar tails
        for (int kk = (n4 << 2); kk < n; ++kk) {
            atomicAdd(&sh[binof(a[kk], invstep, negloinv)], 1u);
            atomicAdd(&sh1b[binof(b[kk], invstep, negloinv)], 1u);
        }
    }
    __syncthreads();
    if (t == 0) {                                    // fold bin 1000 -> 999
        sh[NX - 1] += sh[NX];
        sh1b[NX - 1] += sh1b[NX];
    }
    __syncthreads();
    for (int i2 = t; i2 < NX; i2 += HT) {
        unsigned int ca = sh[i2];
        unsigned int cb = sh1b[i2];
        if (ca) atomicAdd(&g_hist[0][i2], ca);
        if (cb) atomicAdd(&g_hist[1][i2], cb);
    }
    __syncthreads();

    // ---------------- last-arriving block: scan + trapz + reset -------------
    if (t == 0) {
        __threadfence();
        s_last = (atomicAdd(&g_ticket, 1u) == HB - 1u) ? 1u : 0u;
    }
    __syncthreads();
    if (!s_last) return;
    __threadfence();

    // each of 512 threads owns 2 bins of each CDF
    unsigned int c0a[2], c1a[2];
    int bse = 2 * t;
    #pragma unroll
    for (int q = 0; q < 2; ++q) {
        int idx = bse + q;
        c0a[q] = (idx < NX) ? __ldcg(&g_hist[0][idx]) : 0u;
        c1a[q] = (idx < NX) ? __ldcg(&g_hist[1][idx]) : 0u;
    }
    c0a[1] += c0a[0];
    c1a[1] += c1a[0];
    unsigned int tc = c0a[1], td = c1a[1];
    unsigned int ic = tc, id = td;
    #pragma unroll
    for (int o = 1; o < 32; o <<= 1) {
        unsigned int u0 = __shfl_up_sync(0xFFFFFFFFu, ic, o);
        unsigned int u1 = __shfl_up_sync(0xFFFFFFFFu, id, o);
        if (lane >= o) { ic += u0; id += u1; }
    }
    unsigned int exc = ic - tc, exd = id - td;   // exclusive within warp
    if (lane == 31) { ws0[w] = ic; ws1[w] = id; }
    __syncthreads();
    if (w == 0) {
        unsigned int v0 = (lane < 16) ? ws0[lane] : 0u;
        unsigned int v1 = (lane < 16) ? ws1[lane] : 0u;
        #pragma unroll
        for (int o = 1; o < 16; o <<= 1) {
            unsigned int u0 = __shfl_up_sync(0xFFFFFFFFu, v0, o);
            unsigned int u1 = __shfl_up_sync(0xFFFFFFFFu, v1, o);
            if (lane >= o) { v0 += u0; v1 += u1; }
        }
        if (lane < 16) { ws0[lane] = v0; ws1[lane] = v1; }
    }
    __syncthreads();
    unsigned int wb0 = w ? ws0[w - 1] : 0u;
    unsigned int wb1 = w ? ws1[w - 1] : 0u;
    exc += wb0; exd += wb1;
    #pragma unroll
    for (int q = 0; q < 2; ++q) {
        int idx = bse + q;
        if (idx < NX) { sh[idx] = exc + c0a[q]; sh1b[idx] = exd + c1a[q]; }
    }
    __syncthreads();

    // trapz over 999 intervals, f32 term rounding matches reference
    float nf = (float)n;
    double acc = 0.0;
    for (int j = t; j < NX - 1; j += HT) {
        float cp0 = (float)sh[j] / nf;
        float ct0 = (float)sh1b[j] / nf;
        float cp1 = (float)sh[j + 1] / nf;
        float ct1 = (float)sh1b[j + 1] / nf;
        float y0 = cp0 - ct0; y0 = y0 * y0;
        float y1 = cp1 - ct1; y1 = y1 * y1;
        float dx = xval(j + 1, lo, hi, step) - xval(j, lo, hi, step);
        acc += (double)(0.5f * (y0 + y1) * dx);
    }
    for (int o = 16; o; o >>= 1)
        acc += __shfl_xor_sync(0xFFFFFFFFu, acc, o);
    if (lane == 0) sd[w] = acc;
    __syncthreads();
    if (t == 0) {
        double s = 0.0;
        #pragma unroll
        for (int q = 0; q < 16; ++q) s += sd[q];
        out[0] = (float)s;
    }

    // ---- reset all device state for the next graph replay ----
    __syncthreads();
    for (int i3 = t; i3 < 2 * NX; i3 += HT)
        ((unsigned int*)g_hist)[i3] = 0u;
    if (t == 0) {
        g_negmin_bits = 0u;
        g_max_bits = 0u;
        g_ticket = 0u;
        g_bar = 0u;
        g_workA = 0u;
        g_workB = 0u;
    }
}

// ---------------- launch ----------------------------------------------------
extern "C" void kernel_launch(void* const* d_in, const int* in_sizes, int n_in,
                              void* d_out, int out_size) {
    const float* p = (const float*)d_in[0];
    const float* tg = (const float*)d_in[1];
    int n = in_sizes[0];

    crps_k<<<HB, HT>>>(p, tg, n, (float*)d_out);
}

// round 13
// speedup vs baseline: 1.3265x; 1.3265x over previous
#include <cuda_runtime.h>
#include <math_constants.h>

#define NX   1000
#define NP   1008        // padded shared hist (bin 1000 possible; folded into 999)
#define HB   592         // grid: 4 CTAs/SM x 148 SMs -> ALL resident (barrier-safe)
#define HT   512
#define HALF (HB / 2)    // blocks [0,296) -> array a, [296,592) -> array b

// ---------------- device-global scratch (zero-init is the neutral state) ----
__device__ unsigned int g_negmin_bits;   // holds max(~enc(v))  -> min value
__device__ unsigned int g_max_bits;      // holds max( enc(v))  -> max value
__device__ unsigned int g_hist[2][NX];
__device__ unsigned int g_bar;           // grid barrier counter
__device__ unsigned int g_ticket;        // last-block detection

__device__ __forceinline__ unsigned int enc_f(float f) {
    unsigned int u = __float_as_uint(f);
    return (u & 0x80000000u) ? ~u : (u | 0x80000000u);
}
__device__ __forceinline__ float dec_f(unsigned int u) {
    u = (u & 0x80000000u) ? (u & 0x7FFFFFFFu) : ~u;
    return __uint_as_float(u);
}

// The linspace grid point, matching f32 "lo + j*step" with exact endpoint.
__device__ __forceinline__ float xval(int j, float lo, float hi, float step) {
    return (j >= NX - 1) ? hi : fmaf((float)j, step, lo);
}

// Cheap bin: ceil_to_int((v-lo)/step), NO clamp — j in [0,1000]; padded
// shared hist absorbs 1000, folded into 999 at flush (exact).
__device__ __forceinline__ int binof(float v, float invstep, float negloinv) {
    return __float2int_ru(fmaf(v, invstep, negloinv));   // F2I.RP
}

__device__ __forceinline__ void mm4(float4 v, float& mn, float& mx) {
    mn = fminf(mn, fminf(fminf(v.x, v.y), fminf(v.z, v.w)));
    mx = fmaxf(mx, fmaxf(fmaxf(v.x, v.y), fmaxf(v.z, v.w)));
}
__device__ __forceinline__ void hist4(float4 v, unsigned int* h,
                                      float invstep, float negloinv) {
    atomicAdd(&h[binof(v.x, invstep, negloinv)], 1u);
    atomicAdd(&h[binof(v.y, invstep, negloinv)], 1u);
    atomicAdd(&h[binof(v.z, invstep, negloinv)], 1u);
    atomicAdd(&h[binof(v.w, invstep, negloinv)], 1u);
}

// =================== single fused persistent kernel =========================
__global__ void __launch_bounds__(HT, 4) crps_k(const float* __restrict__ a,
                                                const float* __restrict__ b,
                                                int n, float* __restrict__ out) {
    __shared__ unsigned int sh[NP];      // this block's histogram
    __shared__ unsigned int sh2[NP];     // used only by the finishing block
    __shared__ float smn[16], smx[16];
    __shared__ double sd[16];
    __shared__ unsigned int ws0[16], ws1[16];
    __shared__ unsigned int s_last;

    const int t   = threadIdx.x;
    const int bid = blockIdx.x;
    const int lane = t & 31, w = t >> 5;

    const int which = (bid < HALF) ? 0 : 1;
    const int vbid  = bid - which * HALF;
    const float* __restrict__ src = which ? b : a;
    const float4* __restrict__ s4 = (const float4*)src;

    const int n4   = n >> 2;
    const int S    = HALF * HT;           // stride within one array's block set
    const int base = vbid * HT + t;

    for (int i = t; i < NP; i += HT) sh[i] = 0u;   // zero hist early

    // ---------------- phase A: min/max over this block's array --------------
    float mn = CUDART_INF_F, mx = -CUDART_INF_F;
    int i = base;
    for (; i + 3 * S < n4; i += 4 * S) {
        float4 v0 = s4[i];
        float4 v1 = s4[i + S];
        float4 v2 = s4[i + 2 * S];
        float4 v3 = s4[i + 3 * S];
        mm4(v0, mn, mx);
        mm4(v1, mn, mx);
        mm4(v2, mn, mx);
        mm4(v3, mn, mx);
    }
    for (; i < n4; i += S) {
        float4 v0 = s4[i];
        mm4(v0, mn, mx);
    }
    if (bid == 0 && t == 0) {            // scalar tail (n % 4), both arrays
        for (int k = (n4 << 2); k < n; ++k) {
            mn = fminf(mn, fminf(a[k], b[k]));
            mx = fmaxf(mx, fmaxf(a[k], b[k]));
        }
    }
    for (int o = 16; o; o >>= 1) {
        mn = fminf(mn, __shfl_xor_sync(0xFFFFFFFFu, mn, o));
        mx = fmaxf(mx, __shfl_xor_sync(0xFFFFFFFFu, mx, o));
    }
    if (lane == 0) { smn[w] = mn; smx[w] = mx; }
    __syncthreads();
    if (t < 32) {
        mn = (t < 16) ? smn[t] : CUDART_INF_F;
        mx = (t < 16) ? smx[t] : -CUDART_INF_F;
        for (int o = 16; o; o >>= 1) {
            mn = fminf(mn, __shfl_xor_sync(0xFFFFFFFFu, mn, o));
            mx = fmaxf(mx, __shfl_xor_sync(0xFFFFFFFFu, mx, o));
        }
        if (t == 0) {
            atomicMax(&g_negmin_bits, ~enc_f(mn));
            atomicMax(&g_max_bits, enc_f(mx));
        }
    }
    __syncthreads();

    // ---------------- grid barrier (all 592 CTAs resident -> safe) ----------
    if (t == 0) {
        __threadfence();
        atomicAdd(&g_bar, 1u);
        while (*((volatile unsigned int*)&g_bar) < HB) __nanosleep(64);
    }
    __syncthreads();
    __threadfence();

    // ---------------- phase B: histogram this block's array -----------------
    float lo = dec_f(~__ldcg(&g_negmin_bits));
    float hi = dec_f(__ldcg(&g_max_bits));
    float step = (hi - lo) / (float)(NX - 1);
    float invstep = (step > 0.0f) ? (1.0f / step) : 0.0f;
    float negloinv = -lo * invstep;

    // walk this thread's phase-A index sequence IN REVERSE (L1 + L2 hot),
    // 4-way unrolled: 4 independent LDG.128 in flight to cover L2 latency
    int k = (n4 - 1 - base) / S;
    i = base + k * S;
    for (; i - 3 * S >= base; i -= 4 * S) {
        float4 v0 = s4[i];
        float4 v1 = s4[i - S];
        float4 v2 = s4[i - 2 * S];
        float4 v3 = s4[i - 3 * S];
        hist4(v0, sh, invstep, negloinv);
        hist4(v1, sh, invstep, negloinv);
        hist4(v2, sh, invstep, negloinv);
        hist4(v3, sh, invstep, negloinv);
    }
    for (; i >= base; i -= S) {
        float4 v0 = s4[i];
        hist4(v0, sh, invstep, negloinv);
    }
    if (t == 0 && (bid == 0 || bid == HALF)) {   // scalar tails into own hist
        const float* s = which ? b : a;
        for (int kk = (n4 << 2); kk < n; ++kk)
            atomicAdd(&sh[binof(s[kk], invstep, negloinv)], 1u);
    }
    __syncthreads();
    if (t == 0) sh[NX - 1] += sh[NX];            // fold bin 1000 -> 999
    __syncthreads();
    for (int i2 = t; i2 < NX; i2 += HT)
        atomicAdd(&g_hist[which][i2], sh[i2]);
    __syncthreads();

    // ---------------- last-arriving block: scan + trapz + reset -------------
    if (t == 0) {
        __threadfence();
        s_last = (atomicAdd(&g_ticket, 1u) == HB - 1u) ? 1u : 0u;
    }
    __syncthreads();
    if (!s_last) return;
    __threadfence();

    // each of 512 threads owns 2 bins of each CDF
    unsigned int c0[2], c1[2];
    int bse = 2 * t;
    #pragma unroll
    for (int q = 0; q < 2; ++q) {
        int idx = bse + q;
        c0[q] = (idx < NX) ? __ldcg(&g_hist[0][idx]) : 0u;
        c1[q] = (idx < NX) ? __ldcg(&g_hist[1][idx]) : 0u;
    }
    c0[1] += c0[0];
    c1[1] += c1[0];
    unsigned int tc = c0[1], td = c1[1];
    unsigned int ic = tc, id = td;
    #pragma unroll
    for (int o = 1; o < 32; o <<= 1) {
        unsigned int u0 = __shfl_up_sync(0xFFFFFFFFu, ic, o);
        unsigned int u1 = __shfl_up_sync(0xFFFFFFFFu, id, o);
        if (lane >= o) { ic += u0; id += u1; }
    }
    unsigned int exc = ic - tc, exd = id - td;   // exclusive within warp
    if (lane == 31) { ws0[w] = ic; ws1[w] = id; }
    __syncthreads();
    if (w == 0) {
        unsigned int v0 = (lane < 16) ? ws0[lane] : 0u;
        unsigned int v1 = (lane < 16) ? ws1[lane] : 0u;
        #pragma unroll
        for (int o = 1; o < 16; o <<= 1) {
            unsigned int u0 = __shfl_up_sync(0xFFFFFFFFu, v0, o);
            unsigned int u1 = __shfl_up_sync(0xFFFFFFFFu, v1, o);
            if (lane >= o) { v0 += u0; v1 += u1; }
        }
        if (lane < 16) { ws0[lane] = v0; ws1[lane] = v1; }
    }
    __syncthreads();
    unsigned int wb0 = w ? ws0[w - 1] : 0u;
    unsigned int wb1 = w ? ws1[w - 1] : 0u;
    exc += wb0; exd += wb1;
    #pragma unroll
    for (int q = 0; q < 2; ++q) {
        int idx = bse + q;
        if (idx < NX) { sh[idx] = exc + c0[q]; sh2[idx] = exd + c1[q]; }
    }
    __syncthreads();

    // trapz over 999 intervals, f32 term rounding matches reference
    float nf = (float)n;
    double acc = 0.0;
    for (int j = t; j < NX - 1; j += HT) {
        float cp0 = (float)sh[j] / nf;
        float ct0 = (float)sh2[j] / nf;
        float cp1 = (float)sh[j + 1] / nf;
        float ct1 = (float)sh2[j + 1] / nf;
        float y0 = cp0 - ct0; y0 = y0 * y0;
        float y1 = cp1 - ct1; y1 = y1 * y1;
        float dx = xval(j + 1, lo, hi, step) - xval(j, lo, hi, step);
        acc += (double)(0.5f * (y0 + y1) * dx);
    }
    for (int o = 16; o; o >>= 1)
        acc += __shfl_xor_sync(0xFFFFFFFFu, acc, o);
    if (lane == 0) sd[w] = acc;
    __syncthreads();
    if (t == 0) {
        double s = 0.0;
        #pragma unroll
        for (int q = 0; q < 16; ++q) s += sd[q];
        out[0] = (float)s;
    }

    // ---- reset all device state for the next graph replay ----
    __syncthreads();
    for (int i3 = t; i3 < 2 * NX; i3 += HT)
        ((unsigned int*)g_hist)[i3] = 0u;
    if (t == 0) {
        g_negmin_bits = 0u;
        g_max_bits = 0u;
        g_ticket = 0u;
        g_bar = 0u;
    }
}

// ---------------- launch ----------------------------------------------------
extern "C" void kernel_launch(void* const* d_in, const int* in_sizes, int n_in,
                              void* d_out, int out_size) {
    const float* p = (const float*)d_in[0];
    const float* tg = (const float*)d_in[1];
    int n = in_sizes[0];

    crps_k<<<HB, HT>>>(p, tg, n, (float*)d_out);
}

// round 15
// speedup vs baseline: 1.3449x; 1.0139x over previous
#include <cuda_runtime.h>
#include <math_constants.h>

#define NX   1000
#define NP   1008        // padded shared hist (bin 1000 possible; folded into 999)
#define HB   592         // grid: 4 CTAs/SM x 148 SMs -> ALL resident (barrier-safe)
#define HT   512
#define HALF (HB / 2)    // blocks [0,296) -> array a, [296,592) -> array b

// ---------------- device-global scratch (zero-init is the neutral state) ----
__device__ unsigned int g_negmin_bits;   // holds max(~enc(v))  -> min value
__device__ unsigned int g_max_bits;      // holds max( enc(v))  -> max value
__device__ unsigned int g_hist[2][NX];
__device__ unsigned int g_bar;           // grid barrier counter
__device__ unsigned int g_ticket;        // last-block detection

__device__ __forceinline__ unsigned int enc_f(float f) {
    unsigned int u = __float_as_uint(f);
    return (u & 0x80000000u) ? ~u : (u | 0x80000000u);
}
__device__ __forceinline__ float dec_f(unsigned int u) {
    u = (u & 0x80000000u) ? (u & 0x7FFFFFFFu) : ~u;
    return __uint_as_float(u);
}

// The linspace grid point, matching f32 "lo + j*step" with exact endpoint.
__device__ __forceinline__ float xval(int j, float lo, float hi, float step) {
    return (j >= NX - 1) ? hi : fmaf((float)j, step, lo);
}

// Cheap bin: ceil_to_int((v-lo)/step), NO clamp — j in [0,1000]; padded
// shared hist absorbs 1000, folded into 999 at flush (exact).
__device__ __forceinline__ int binof(float v, float invstep, float negloinv) {
    return __float2int_ru(fmaf(v, invstep, negloinv));   // F2I.RP
}

__device__ __forceinline__ void mm4(float4 v, float& mn, float& mx) {
    mn = fminf(mn, fminf(fminf(v.x, v.y), fminf(v.z, v.w)));
    mx = fmaxf(mx, fmaxf(fmaxf(v.x, v.y), fmaxf(v.z, v.w)));
}
__device__ __forceinline__ void hist4(float4 v, unsigned int* h,
                                      float invstep, float negloinv) {
    atomicAdd(&h[binof(v.x, invstep, negloinv)], 1u);
    atomicAdd(&h[binof(v.y, invstep, negloinv)], 1u);
    atomicAdd(&h[binof(v.z, invstep, negloinv)], 1u);
    atomicAdd(&h[binof(v.w, invstep, negloinv)], 1u);
}

// =================== single fused persistent kernel =========================
__global__ void __launch_bounds__(HT, 4) crps_k(const float* __restrict__ a,
                                                const float* __restrict__ b,
                                                int n, float* __restrict__ out) {
    __shared__ unsigned int sh[NP];      // this block's histogram
    __shared__ unsigned int sh2[NP];     // used only by the finishing block
    __shared__ float smn[16], smx[16];
    __shared__ double sd[16];
    __shared__ unsigned int ws0[16], ws1[16];
    __shared__ unsigned int s_last;

    const int t   = threadIdx.x;
    const int bid = blockIdx.x;
    const int lane = t & 31, w = t >> 5;

    const int which = (bid < HALF) ? 0 : 1;
    const int vbid  = bid - which * HALF;
    const float* __restrict__ src = which ? b : a;
    const float4* __restrict__ s4 = (const float4*)src;

    const int n4   = n >> 2;
    const int S    = HALF * HT;           // stride within one array's block set
    const int base = vbid * HT + t;

    for (int i = t; i < NP; i += HT) sh[i] = 0u;   // zero hist early

    // ---------------- phase A: min/max over this block's array --------------
    float mn = CUDART_INF_F, mx = -CUDART_INF_F;
    int i = base;
    for (; i + 3 * S < n4; i += 4 * S) {
        float4 v0 = s4[i];
        float4 v1 = s4[i + S];
        float4 v2 = s4[i + 2 * S];
        float4 v3 = s4[i + 3 * S];
        mm4(v0, mn, mx);
        mm4(v1, mn, mx);
        mm4(v2, mn, mx);
        mm4(v3, mn, mx);
    }
    for (; i < n4; i += S) {
        float4 v0 = s4[i];
        mm4(v0, mn, mx);
    }
    if (bid == 0 && t == 0) {            // scalar tail (n % 4), both arrays
        for (int k = (n4 << 2); k < n; ++k) {
            mn = fminf(mn, fminf(a[k], b[k]));
            mx = fmaxf(mx, fmaxf(a[k], b[k]));
        }
    }
    for (int o = 16; o; o >>= 1) {
        mn = fminf(mn, __shfl_xor_sync(0xFFFFFFFFu, mn, o));
        mx = fmaxf(mx, __shfl_xor_sync(0xFFFFFFFFu, mx, o));
    }
    if (lane == 0) { smn[w] = mn; smx[w] = mx; }
    __syncthreads();
    if (t < 32) {
        mn = (t < 16) ? smn[t] : CUDART_INF_F;
        mx = (t < 16) ? smx[t] : -CUDART_INF_F;
        for (int o = 16; o; o >>= 1) {
            mn = fminf(mn, __shfl_xor_sync(0xFFFFFFFFu, mn, o));
            mx = fmaxf(mx, __shfl_xor_sync(0xFFFFFFFFu, mx, o));
        }
        if (t == 0) {
            atomicMax(&g_negmin_bits, ~enc_f(mn));
            atomicMax(&g_max_bits, enc_f(mx));
        }
    }
    __syncthreads();

    // ---------------- grid barrier (all 592 CTAs resident -> safe) ----------
    if (t == 0) {
        __threadfence();
        atomicAdd(&g_bar, 1u);
        while (*((volatile unsigned int*)&g_bar) < HB) __nanosleep(32);
    }
    __syncthreads();
    __threadfence();

    // ---------------- phase B: histogram this block's array -----------------
    float lo = dec_f(~__ldcg(&g_negmin_bits));
    float hi = dec_f(__ldcg(&g_max_bits));
    float step = (hi - lo) / (float)(NX - 1);
    float invstep = (step > 0.0f) ? (1.0f / step) : 0.0f;
    float negloinv = -lo * invstep;

    // walk this thread's phase-A index sequence IN REVERSE (L1 + L2 hot)
    int k = (n4 - 1 - base) / S;
    i = base + k * S;
    for (; i - S >= base; i -= 2 * S) {
        float4 v0 = s4[i];
        float4 v1 = s4[i - S];
        hist4(v0, sh, invstep, negloinv);
        hist4(v1, sh, invstep, negloinv);
    }
    for (; i >= base; i -= S) {
        float4 v0 = s4[i];
        hist4(v0, sh, invstep, negloinv);
    }
    if (t == 0 && (bid == 0 || bid == HALF)) {   // scalar tails into own hist
        const float* s = which ? b : a;
        for (int kk = (n4 << 2); kk < n; ++kk)
            atomicAdd(&sh[binof(s[kk], invstep, negloinv)], 1u);
    }
    __syncthreads();
    if (t == 0) sh[NX - 1] += sh[NX];            // fold bin 1000 -> 999
    __syncthreads();
    for (int i2 = t; i2 < NX; i2 += HT)
        atomicAdd(&g_hist[which][i2], sh[i2]);
    __syncthreads();

    // ---------------- last-arriving block: scan + trapz + reset -------------
    if (t == 0) {
        __threadfence();
        s_last = (atomicAdd(&g_ticket, 1u) == HB - 1u) ? 1u : 0u;
    }
    __syncthreads();
    if (!s_last) return;
    __threadfence();

    // each of 512 threads owns 2 bins of each CDF
    unsigned int c0[2], c1[2];
    int bse = 2 * t;
    #pragma unroll
    for (int q = 0; q < 2; ++q) {
        int idx = bse + q;
        c0[q] = (idx < NX) ? __ldcg(&g_hist[0][idx]) : 0u;
        c1[q] = (idx < NX) ? __ldcg(&g_hist[1][idx]) : 0u;
    }
    c0[1] += c0[0];
    c1[1] += c1[0];
    unsigned int tc = c0[1], td = c1[1];
    unsigned int ic = tc, id = td;
    #pragma unroll
    for (int o = 1; o < 32; o <<= 1) {
        unsigned int u0 = __shfl_up_sync(0xFFFFFFFFu, ic, o);
        unsigned int u1 = __shfl_up_sync(0xFFFFFFFFu, id, o);
        if (lane >= o) { ic += u0; id += u1; }
    }
    unsigned int exc = ic - tc, exd = id - td;   // exclusive within warp
    if (lane == 31) { ws0[w] = ic; ws1[w] = id; }
    __syncthreads();
    if (w == 0) {
        unsigned int v0 = (lane < 16) ? ws0[lane] : 0u;
        unsigned int v1 = (lane < 16) ? ws1[lane] : 0u;
        #pragma unroll
        for (int o = 1; o < 16; o <<= 1) {
            unsigned int u0 = __shfl_up_sync(0xFFFFFFFFu, v0, o);
            unsigned int u1 = __shfl_up_sync(0xFFFFFFFFu, v1, o);
            if (lane >= o) { v0 += u0; v1 += u1; }
        }
        if (lane < 16) { ws0[lane] = v0; ws1[lane] = v1; }
    }
    __syncthreads();
    unsigned int wb0 = w ? ws0[w - 1] : 0u;
    unsigned int wb1 = w ? ws1[w - 1] : 0u;
    exc += wb0; exd += wb1;
    #pragma unroll
    for (int q = 0; q < 2; ++q) {
        int idx = bse + q;
        if (idx < NX) { sh[idx] = exc + c0[q]; sh2[idx] = exd + c1[q]; }
    }
    __syncthreads();

    // trapz over 999 intervals, f32 term rounding matches reference
    float nf = (float)n;
    double acc = 0.0;
    for (int j = t; j < NX - 1; j += HT) {
        float cp0 = (float)sh[j] / nf;
        float ct0 = (float)sh2[j] / nf;
        float cp1 = (float)sh[j + 1] / nf;
        float ct1 = (float)sh2[j + 1] / nf;
        float y0 = cp0 - ct0; y0 = y0 * y0;
        float y1 = cp1 - ct1; y1 = y1 * y1;
        float dx = xval(j + 1, lo, hi, step) - xval(j, lo, hi, step);
        acc += (double)(0.5f * (y0 + y1) * dx);
    }
    for (int o = 16; o; o >>= 1)
        acc += __shfl_xor_sync(0xFFFFFFFFu, acc, o);
    if (lane == 0) sd[w] = acc;
    __syncthreads();
    if (t == 0) {
        double s = 0.0;
        #pragma unroll
        for (int q = 0; q < 16; ++q) s += sd[q];
        out[0] = (float)s;
    }

    // ---- reset all device state for the next graph replay ----
    __syncthreads();
    for (int i3 = t; i3 < 2 * NX; i3 += HT)
        ((unsigned int*)g_hist)[i3] = 0u;
    if (t == 0) {
        g_negmin_bits = 0u;
        g_max_bits = 0u;
        g_ticket = 0u;
        g_bar = 0u;
    }
}

// ---------------- launch ----------------------------------------------------
extern "C" void kernel_launch(void* const* d_in, const int* in_sizes, int n_in,
                              void* d_out, int out_size) {
    const float* p = (const float*)d_in[0];
    const float* tg = (const float*)d_in[1];
    int n = in_sizes[0];

    crps_k<<<HB, HT>>>(p, tg, n, (float*)d_out);
}